// round 11
// baseline (speedup 1.0000x reference)
#include <cuda_runtime.h>
#include <cuda_fp16.h>
#include <math.h>
#include <stdint.h>

#define D_DIM 128
#define K_DIM 512
#define TM 32
#define NTHREADS 256
#define BETA_SM 10.0f

// smem byte offsets
#define USTR 516
#define OFF_U 0                      // 32 x 516 x 4 = 66048
#define OFF_LATH 66048               // 32 rows x 256 B = 8192
#define ALSTR 256                    // latent fp16 row stride (bytes)
#define OFF_EMB  74240               // 128 x 272 = 34816
#define ESTR 272                     // 16B-aligned k-row stride (bytes)
#define OFF_ESQ  109056              // 512 x 4 = 2048
#define OFF_ROWSQ 111104             // 32 x 4 = 128
#define SMEM_BYTES 111232

// ---------------- device globals (zero at load; self-reset each call) ----------------
__device__ double g_sq_sum;
__device__ double g_mind_sum;
__device__ unsigned int g_counts[K_DIM];
__device__ unsigned int g_done;

// ---------------- single fused kernel ----------------
__global__ void __launch_bounds__(NTHREADS, 2) vq_kernel(
    const float* __restrict__ latents,
    const float* __restrict__ emb,
    float* __restrict__ out_q,
    float* __restrict__ out_ind,
    float* __restrict__ out_soft,
    float* __restrict__ out_vq,
    float* __restrict__ out_ent,
    float* __restrict__ out_cm)
{
    extern __shared__ __align__(16) unsigned char smem[];
    float*   s_u     = (float*)smem;                       // 32 x USTR
    __half2* s_lath  = (__half2*)(smem + OFF_LATH);        // 32 x 64 (256 B rows)
    float*   s_esq   = (float*)(smem + OFF_ESQ);           // 512 (approx)
    float*   s_rowsq = (float*)(smem + OFF_ROWSQ);         // 32 (exact chains)

    const int tid = threadIdx.x;
    const int wid = tid >> 5, tx = tid & 31;
    const long long row0 = (long long)blockIdx.x * TM;

    // --- stage latents as fp16 (d,d+1) pairs ---
    {
        const float4* lat4 = (const float4*)(latents + row0 * D_DIM);
#pragma unroll
        for (int it = 0; it < 4; ++it) {
            int idx = it * NTHREADS + tid;      // 1024 float4
            int row = idx >> 5, c4 = idx & 31;
            float4 x = lat4[idx];
            s_lath[row * 64 + c4 * 2]     = __floats2half2_rn(x.x, x.y);
            s_lath[row * 64 + c4 * 2 + 1] = __floats2half2_rn(x.z, x.w);
        }
    }
    // --- rowsq: exact sequential reference chain (rescue/cm only) ---
    if (tid < TM) {
        const float* lr = latents + (row0 + tid) * D_DIM;
        float s = 0.f;
        for (int d = 0; d < D_DIM; ++d)
            s = __fadd_rn(s, __fmul_rn(lr[d], lr[d]));
        s_rowsq[tid] = s;
    }

    const int r0 = wid * 4;
    float usum[4] = {0.f, 0.f, 0.f, 0.f};
    float umax[4] = {0.f, 0.f, 0.f, 0.f};
    const __half2 hz = __float2half2_rn(0.f);

    // precomputed GEMM base pointers (A row stride = ALSTR = 256 bytes)
    const unsigned char* aBase = smem + OFF_LATH + (size_t)r0 * ALSTR;
    const unsigned char* bBase = smem + OFF_EMB + (size_t)tx * ESTR;      // j stride 32*ESTR

    // ---- 4 k-quarters: fill emb fp16 (x256), HFMA2 LDS.128 GEMM, u = exp ----
    for (int q = 0; q < 4; ++q) {
        __syncthreads();   // previous quarter's reads done
        {
            // fill: thread -> k row (tid>>1), half the d-range (p*64 floats)
            int k = tid >> 1, p = tid & 1;
            const float4* src = (const float4*)emb + (size_t)(q * 128 + k) * 32 + p * 16;
            unsigned char* dst = smem + OFF_EMB + k * ESTR + p * 128;
            float esq_part = 0.f;
#pragma unroll
            for (int jj = 0; jj < 8; ++jj) {
                float4 v0 = src[2 * jj];
                float4 v1 = src[2 * jj + 1];
                esq_part += v0.x * v0.x + v0.y * v0.y + v0.z * v0.z + v0.w * v0.w;
                esq_part += v1.x * v1.x + v1.y * v1.y + v1.z * v1.z + v1.w * v1.w;
                union { __half2 h[4]; uint4 u; } pk;
                pk.h[0] = __floats2half2_rn(v0.x * 256.f, v0.y * 256.f);
                pk.h[1] = __floats2half2_rn(v0.z * 256.f, v0.w * 256.f);
                pk.h[2] = __floats2half2_rn(v1.x * 256.f, v1.y * 256.f);
                pk.h[3] = __floats2half2_rn(v1.z * 256.f, v1.w * 256.f);
                *(uint4*)(dst + jj * 16) = pk.u;
            }
            esq_part += __shfl_xor_sync(0xffffffffu, esq_part, 1);
            if (p == 0) s_esq[q * 128 + k] = esq_part;
        }
        __syncthreads();

        float accF[4][4];
        __half2 accH[4][4];
#pragma unroll
        for (int i = 0; i < 4; ++i)
#pragma unroll
            for (int j = 0; j < 4; ++j) { accF[i][j] = 0.f; accH[i][j] = hz; }

#pragma unroll 1
        for (int dblk = 0; dblk < 4; ++dblk) {
#pragma unroll
            for (int dq = 0; dq < 4; ++dq) {
                int off = dblk * 64 + dq * 16;     // byte offset within 256-B d range
                union { __half2 h[4]; uint4 u; } av[4], bv[4];
#pragma unroll
                for (int i = 0; i < 4; ++i)
                    av[i].u = *(const uint4*)(aBase + i * ALSTR + off);   // broadcast
#pragma unroll
                for (int j = 0; j < 4; ++j)
                    bv[j].u = *(const uint4*)(bBase + j * (32 * ESTR) + off);
#pragma unroll
                for (int i = 0; i < 4; ++i)
#pragma unroll
                    for (int j = 0; j < 4; ++j) {
                        accH[i][j] = __hfma2(av[i].h[0], bv[j].h[0], accH[i][j]);
                        accH[i][j] = __hfma2(av[i].h[1], bv[j].h[1], accH[i][j]);
                        accH[i][j] = __hfma2(av[i].h[2], bv[j].h[2], accH[i][j]);
                        accH[i][j] = __hfma2(av[i].h[3], bv[j].h[3], accH[i][j]);
                    }
            }
            // promote to fp32 every 32 d
#pragma unroll
            for (int i = 0; i < 4; ++i)
#pragma unroll
                for (int j = 0; j < 4; ++j) {
                    float2 f = __half22float2(accH[i][j]);
                    accF[i][j] += f.x + f.y;
                    accH[i][j] = hz;
                }
        }

        // u = exp(-10 * (esq - dotS/128)); track sum/max per row
#pragma unroll
        for (int j = 0; j < 4; ++j) {
            int k = q * 128 + tx + 32 * j;
            float es = s_esq[k];
#pragma unroll
            for (int i = 0; i < 4; ++i) {
                float dsh = __fmaf_rn(accF[i][j], -0.0078125f, es);
                float u = __expf(-BETA_SM * dsh);
                s_u[(r0 + i) * USTR + k] = u;
                usum[i] += u;
                umax[i] = fmaxf(umax[i], u);
            }
        }
    }

    // ---- warp-reduce per-row sum/max ----
#pragma unroll
    for (int i = 0; i < 4; ++i)
#pragma unroll
        for (int o = 16; o; o >>= 1) {
            usum[i] += __shfl_xor_sync(0xffffffffu, usum[i], o);
            umax[i] = fmaxf(umax[i], __shfl_xor_sync(0xffffffffu, umax[i], o));
        }

    // ---- phase 2: probs, exact-rescue argmin, outputs ----
    float warp_sq = 0.f, warp_cm = 0.f;

#pragma unroll 1
    for (int i = 0; i < 4; ++i) {
        int r = r0 + i;
        long long rg = row0 + r;
        const float* ur = s_u + r * USTR;
        float inv = 1.0f / usum[i];
        float thr = umax[i] * 0.9955f;      // == dist margin ~4.5e-4 (validated r8/r9)

        float* os = out_soft + rg * K_DIM;
#pragma unroll
        for (int t = 0; t < 16; ++t)
            os[tx + 32 * t] = ur[tx + 32 * t] * inv;

        const float rsq = s_rowsq[r];
        const float* lrow = latents + rg * D_DIM;
        float bestd = 3.4e38f;
        int bestk = 0x7fffffff;
#pragma unroll 1
        for (int t = 0; t < 16; ++t) {
            if (ur[tx + 32 * t] >= thr) {
                int k = tx + 32 * t;
                const float* er = emb + (size_t)k * D_DIM;
                float a = 0.f, qq = 0.f;
                for (int d = 0; d < D_DIM; ++d) {
                    float ev = er[d];
                    a = __fmaf_rn(lrow[d], ev, a);
                    qq = __fadd_rn(qq, __fmul_rn(ev, ev));
                }
                float de = __fmaf_rn(-2.f, a, __fadd_rn(rsq, qq));
                if (de < bestd || (de == bestd && k < bestk)) { bestd = de; bestk = k; }
            }
        }
#pragma unroll
        for (int o = 16; o; o >>= 1) {
            float od = __shfl_xor_sync(0xffffffffu, bestd, o);
            int   ok = __shfl_xor_sync(0xffffffffu, bestk, o);
            if (od < bestd || (od == bestd && ok < bestk)) { bestd = od; bestk = ok; }
        }

        if (tx == 0) {
            atomicAdd(&g_counts[bestk], 1u);
            out_ind[rg] = (float)bestk;
            warp_cm += bestd;
        }

        float4 qv = ((const float4*)emb)[bestk * 32 + tx];
        float4 lv = ((const float4*)lrow)[tx];
        ((float4*)(out_q + rg * D_DIM))[tx] = qv;
        float dx = qv.x - lv.x, dy = qv.y - lv.y, dz = qv.z - lv.z, dw = qv.w - lv.w;
        float sq = dx * dx + dy * dy + dz * dz + dw * dw;
#pragma unroll
        for (int o = 16; o; o >>= 1) sq += __shfl_xor_sync(0xffffffffu, sq, o);
        if (tx == 0) warp_sq += sq;
    }

    if (tx == 0) {
        atomicAdd(&g_sq_sum, (double)warp_sq);
        atomicAdd(&g_mind_sum, (double)warp_cm);
    }

    // ---- last-block finalize: scalars + reset globals ----
    __shared__ int s_last;
    __threadfence();
    __syncthreads();
    if (tid == 0) {
        unsigned int t = atomicAdd(&g_done, 1u);
        s_last = (t == gridDim.x - 1u) ? 1 : 0;
    }
    __syncthreads();
    if (s_last) {
        __threadfence();
        float* red = s_u;   // reuse
        double Bd = (double)gridDim.x * TM;
        float Bf = (float)Bd;
        float p0 = (float)g_counts[tid] / Bf;
        float p1 = (float)g_counts[tid + 256] / Bf;
        red[tid] = -p0 * logf(p0 + 1e-10f) - p1 * logf(p1 + 1e-10f);
        g_counts[tid] = 0u;
        g_counts[tid + 256] = 0u;
        __syncthreads();
        for (int s = 128; s > 0; s >>= 1) {
            if (tid < s) red[tid] += red[tid + s];
            __syncthreads();
        }
        if (tid == 0) {
            out_vq[0]  = (float)((g_sq_sum / (Bd * (double)D_DIM)) * 1.25);
            out_ent[0] = red[0];
            out_cm[0]  = (float)(g_mind_sum / Bd);
            g_sq_sum = 0.0;
            g_mind_sum = 0.0;
            g_done = 0u;
        }
    }
}

extern "C" void kernel_launch(void* const* d_in, const int* in_sizes, int n_in,
                              void* d_out, int out_size)
{
    const float* latents = (const float*)d_in[0];
    const float* emb     = (const float*)d_in[1];
    long long B = (long long)in_sizes[0] / D_DIM;

    float* out      = (float*)d_out;
    float* out_q    = out;
    float* out_vq   = out + B * D_DIM;
    float* out_ent  = out_vq + 1;
    float* out_ind  = out_ent + 1;
    float* out_soft = out_ind + B;
    float* out_cm   = out_soft + B * K_DIM;

    cudaFuncSetAttribute(vq_kernel, cudaFuncAttributeMaxDynamicSharedMemorySize, SMEM_BYTES);

    vq_kernel<<<(unsigned)(B / TM), NTHREADS, SMEM_BYTES>>>(
        latents, emb, out_q, out_ind, out_soft, out_vq, out_ent, out_cm);
}

// round 12
// speedup vs baseline: 1.0504x; 1.0504x over previous
#include <cuda_runtime.h>
#include <cuda_fp16.h>
#include <math.h>
#include <stdint.h>

#define D_DIM 128
#define K_DIM 512
#define TM 32
#define NTHREADS 256
#define BETA_SM 10.0f

// smem byte offsets
#define USTRH 520                    // u row stride (halves) -> 1040 B
#define OFF_U 0                      // 32 x 1040 = 33280
#define OFF_LATH 33280               // 32 x 256 = 8192
#define ALSTR 256
#define OFF_EMB  41472               // 64 x 264 = 16896
#define ESTR 264                     // k-row stride (bytes), LDS.64 conflict-free
#define OFF_ESQ  58368               // 512 x 4 = 2048
#define OFF_ROWSQ 60416              // 32 x 4 = 128
#define SMEM_BYTES 60544             // x3 CTAs = 181632

// ---------------- device globals (zero at load; self-reset each call) ----------------
__device__ double g_sq_sum;
__device__ double g_mind_sum;
__device__ unsigned int g_counts[K_DIM];
__device__ unsigned int g_done;

// ---------------- single fused kernel ----------------
__global__ void __launch_bounds__(NTHREADS, 3) vq_kernel(
    const float* __restrict__ latents,
    const float* __restrict__ emb,
    float* __restrict__ out_q,
    float* __restrict__ out_ind,
    float* __restrict__ out_soft,
    float* __restrict__ out_vq,
    float* __restrict__ out_ent,
    float* __restrict__ out_cm)
{
    extern __shared__ __align__(16) unsigned char smem[];
    __half*  s_uh    = (__half*)smem;                      // 32 x USTRH
    __half2* s_lath  = (__half2*)(smem + OFF_LATH);        // 32 x 64 (256 B rows)
    float*   s_esq   = (float*)(smem + OFF_ESQ);           // 512 (approx)
    float*   s_rowsq = (float*)(smem + OFF_ROWSQ);         // 32 (exact chains)

    const int tid = threadIdx.x;
    const int wid = tid >> 5, tx = tid & 31;
    const long long row0 = (long long)blockIdx.x * TM;

    // --- stage latents as fp16 (d,d+1) pairs ---
    {
        const float4* lat4 = (const float4*)(latents + row0 * D_DIM);
#pragma unroll
        for (int it = 0; it < 4; ++it) {
            int idx = it * NTHREADS + tid;      // 1024 float4
            int row = idx >> 5, c4 = idx & 31;
            float4 x = lat4[idx];
            s_lath[row * 64 + c4 * 2]     = __floats2half2_rn(x.x, x.y);
            s_lath[row * 64 + c4 * 2 + 1] = __floats2half2_rn(x.z, x.w);
        }
    }
    // --- rowsq: exact sequential reference chain (rescue/cm only) ---
    if (tid < TM) {
        const float* lr = latents + (row0 + tid) * D_DIM;
        float s = 0.f;
        for (int d = 0; d < D_DIM; ++d)
            s = __fadd_rn(s, __fmul_rn(lr[d], lr[d]));
        s_rowsq[tid] = s;
    }

    const int r0 = wid * 4;
    float usum[4] = {0.f, 0.f, 0.f, 0.f};
    float umax[4] = {0.f, 0.f, 0.f, 0.f};
    const __half2 hz = __float2half2_rn(0.f);

    const unsigned char* aBase = smem + OFF_LATH + (size_t)r0 * ALSTR;
    const unsigned char* bBase = smem + OFF_EMB + (size_t)tx * ESTR;

    // ---- 8 stages of 64 k-rows: fill fp16 (x256), HFMA2 GEMM, u = exp -> fp16 smem ----
#pragma unroll 1
    for (int s = 0; s < 8; ++s) {
        __syncthreads();   // prior stage's reads done before overwrite
        {
            // fill: 4 threads per k-row, 32 d each
            int t = tid >> 2, p = tid & 3;
            const float4* src = (const float4*)emb + (size_t)(s * 64 + t) * 32 + p * 8;
            unsigned char* dst = smem + OFF_EMB + t * ESTR + p * 64;
            float ep = 0.f;
#pragma unroll
            for (int jj = 0; jj < 8; ++jj) {
                float4 v = src[jj];
                ep += v.x * v.x + v.y * v.y + v.z * v.z + v.w * v.w;
                union { __half2 h[2]; uint2 u; } pk;
                pk.h[0] = __floats2half2_rn(v.x * 256.f, v.y * 256.f);
                pk.h[1] = __floats2half2_rn(v.z * 256.f, v.w * 256.f);
                *(uint2*)(dst + jj * 8) = pk.u;
            }
            ep += __shfl_xor_sync(0xffffffffu, ep, 1);
            ep += __shfl_xor_sync(0xffffffffu, ep, 2);
            if (p == 0) s_esq[s * 64 + t] = ep;
        }
        __syncthreads();

        float accF[4][2];
        __half2 accH[4][2];
#pragma unroll
        for (int i = 0; i < 4; ++i)
#pragma unroll
            for (int j = 0; j < 2; ++j) { accF[i][j] = 0.f; accH[i][j] = hz; }

#pragma unroll 1
        for (int chunk = 0; chunk < 4; ++chunk) {
#pragma unroll
            for (int d8 = 0; d8 < 8; ++d8) {
                int off = (chunk * 8 + d8) * 8;          // 4 d values per iter
                union { __half2 h[2]; uint2 u; } av[4], bv[2];
#pragma unroll
                for (int i = 0; i < 4; ++i)
                    av[i].u = *(const uint2*)(aBase + i * ALSTR + off);   // broadcast
#pragma unroll
                for (int j = 0; j < 2; ++j)
                    bv[j].u = *(const uint2*)(bBase + j * (32 * ESTR) + off);
#pragma unroll
                for (int i = 0; i < 4; ++i)
#pragma unroll
                    for (int j = 0; j < 2; ++j) {
                        accH[i][j] = __hfma2(av[i].h[0], bv[j].h[0], accH[i][j]);
                        accH[i][j] = __hfma2(av[i].h[1], bv[j].h[1], accH[i][j]);
                    }
            }
            // promote to fp32 every 32 d
#pragma unroll
            for (int i = 0; i < 4; ++i)
#pragma unroll
                for (int j = 0; j < 2; ++j) {
                    float2 f = __half22float2(accH[i][j]);
                    accF[i][j] += f.x + f.y;
                    accH[i][j] = hz;
                }
        }

        // u = exp(-10 * (esq - dotS/128)) -> fp16 smem; track sum/max per row
#pragma unroll
        for (int j = 0; j < 2; ++j) {
            int k = s * 64 + tx + 32 * j;
            float es = s_esq[k];
#pragma unroll
            for (int i = 0; i < 4; ++i) {
                float dsh = __fmaf_rn(accF[i][j], -0.0078125f, es);
                float u = __expf(-BETA_SM * dsh);
                s_uh[(r0 + i) * USTRH + k] = __float2half_rn(u);
                usum[i] += u;
                umax[i] = fmaxf(umax[i], u);
            }
        }
    }

    // ---- warp-reduce per-row sum/max ----
#pragma unroll
    for (int i = 0; i < 4; ++i)
#pragma unroll
        for (int o = 16; o; o >>= 1) {
            usum[i] += __shfl_xor_sync(0xffffffffu, usum[i], o);
            umax[i] = fmaxf(umax[i], __shfl_xor_sync(0xffffffffu, umax[i], o));
        }

    // ---- phase 2: probs, exact-rescue argmin, outputs ----
    float warp_sq = 0.f, warp_cm = 0.f;

#pragma unroll 1
    for (int i = 0; i < 4; ++i) {
        int r = r0 + i;
        long long rg = row0 + r;
        const __half* ur = s_uh + r * USTRH;
        float inv = 1.0f / usum[i];
        float thr = umax[i] * 0.994f;       // dist margin ~6e-4 (covers GEMM + fp16-u err)

        float* os = out_soft + rg * K_DIM;
        const float rsq = s_rowsq[r];
        const float* lrow = latents + rg * D_DIM;
        float bestd = 3.4e38f;
        int bestk = 0x7fffffff;
#pragma unroll 1
        for (int t = 0; t < 16; ++t) {
            int k = tx + 32 * t;
            float uv = __half2float(ur[k]);
            os[k] = uv * inv;
            if (uv >= thr) {
                // exact sequential-chain recompute on the reference grid
                const float* er = emb + (size_t)k * D_DIM;
                float a = 0.f, qq = 0.f;
                for (int d = 0; d < D_DIM; ++d) {
                    float ev = er[d];
                    a = __fmaf_rn(lrow[d], ev, a);
                    qq = __fadd_rn(qq, __fmul_rn(ev, ev));
                }
                float de = __fmaf_rn(-2.f, a, __fadd_rn(rsq, qq));
                if (de < bestd || (de == bestd && k < bestk)) { bestd = de; bestk = k; }
            }
        }
#pragma unroll
        for (int o = 16; o; o >>= 1) {
            float od = __shfl_xor_sync(0xffffffffu, bestd, o);
            int   ok = __shfl_xor_sync(0xffffffffu, bestk, o);
            if (od < bestd || (od == bestd && ok < bestk)) { bestd = od; bestk = ok; }
        }

        if (tx == 0) {
            atomicAdd(&g_counts[bestk], 1u);
            out_ind[rg] = (float)bestk;
            warp_cm += bestd;
        }

        float4 qv = ((const float4*)emb)[bestk * 32 + tx];
        float4 lv = ((const float4*)lrow)[tx];
        ((float4*)(out_q + rg * D_DIM))[tx] = qv;
        float dx = qv.x - lv.x, dy = qv.y - lv.y, dz = qv.z - lv.z, dw = qv.w - lv.w;
        float sq = dx * dx + dy * dy + dz * dz + dw * dw;
#pragma unroll
        for (int o = 16; o; o >>= 1) sq += __shfl_xor_sync(0xffffffffu, sq, o);
        if (tx == 0) warp_sq += sq;
    }

    if (tx == 0) {
        atomicAdd(&g_sq_sum, (double)warp_sq);
        atomicAdd(&g_mind_sum, (double)warp_cm);
    }

    // ---- last-block finalize: scalars + reset globals ----
    __shared__ int s_last;
    __threadfence();
    __syncthreads();
    if (tid == 0) {
        unsigned int t = atomicAdd(&g_done, 1u);
        s_last = (t == gridDim.x - 1u) ? 1 : 0;
    }
    __syncthreads();
    if (s_last) {
        __threadfence();
        float* red = (float*)smem;   // reuse u space
        double Bd = (double)gridDim.x * TM;
        float Bf = (float)Bd;
        float p0 = (float)g_counts[tid] / Bf;
        float p1 = (float)g_counts[tid + 256] / Bf;
        red[tid] = -p0 * logf(p0 + 1e-10f) - p1 * logf(p1 + 1e-10f);
        g_counts[tid] = 0u;
        g_counts[tid + 256] = 0u;
        __syncthreads();
        for (int s = 128; s > 0; s >>= 1) {
            if (tid < s) red[tid] += red[tid + s];
            __syncthreads();
        }
        if (tid == 0) {
            out_vq[0]  = (float)((g_sq_sum / (Bd * (double)D_DIM)) * 1.25);
            out_ent[0] = red[0];
            out_cm[0]  = (float)(g_mind_sum / Bd);
            g_sq_sum = 0.0;
            g_mind_sum = 0.0;
            g_done = 0u;
        }
    }
}

extern "C" void kernel_launch(void* const* d_in, const int* in_sizes, int n_in,
                              void* d_out, int out_size)
{
    const float* latents = (const float*)d_in[0];
    const float* emb     = (const float*)d_in[1];
    long long B = (long long)in_sizes[0] / D_DIM;

    float* out      = (float*)d_out;
    float* out_q    = out;
    float* out_vq   = out + B * D_DIM;
    float* out_ent  = out_vq + 1;
    float* out_ind  = out_ent + 1;
    float* out_soft = out_ind + B;
    float* out_cm   = out_soft + B * K_DIM;

    cudaFuncSetAttribute(vq_kernel, cudaFuncAttributeMaxDynamicSharedMemorySize, SMEM_BYTES);

    vq_kernel<<<(unsigned)(B / TM), NTHREADS, SMEM_BYTES>>>(
        latents, emb, out_q, out_ind, out_soft, out_vq, out_ent, out_cm);
}

// round 13
// speedup vs baseline: 1.1338x; 1.0794x over previous
#include <cuda_runtime.h>
#include <cuda_fp16.h>
#include <math.h>
#include <stdint.h>

#define D_DIM 128
#define K_DIM 512
#define TM 64
#define NTHREADS 256
#define BETA_SM 10.0f

// smem byte offsets
#define USTRH 520                    // u row stride (halves) -> 1040 B
#define OFF_U 0                      // 64 x 1040 = 66560
#define OFF_LATH 66560               // 64 x 256 = 16384
#define ALSTR 256
#define OFF_EMB  82944               // 64 x 264 = 16896
#define ESTR 264                     // k-row stride (bytes), LDS.64 conflict-free
#define OFF_ESQ  99840               // 512 x 4 = 2048
#define OFF_ROWSQ 101888             // 64 x 4 = 256
#define SMEM_BYTES 102144            // x2 CTAs = 204288

// ---------------- device globals (zero at load; self-reset each call) ----------------
__device__ double g_sq_sum;
__device__ double g_mind_sum;
__device__ unsigned int g_counts[K_DIM];
__device__ unsigned int g_done;

// ---------------- single fused kernel ----------------
__global__ void __launch_bounds__(NTHREADS, 2) vq_kernel(
    const float* __restrict__ latents,
    const float* __restrict__ emb,
    float* __restrict__ out_q,
    float* __restrict__ out_ind,
    float* __restrict__ out_soft,
    float* __restrict__ out_vq,
    float* __restrict__ out_ent,
    float* __restrict__ out_cm)
{
    extern __shared__ __align__(16) unsigned char smem[];
    __half*  s_uh    = (__half*)smem;                      // 64 x USTRH
    __half2* s_lath  = (__half2*)(smem + OFF_LATH);        // 64 x 64 (256 B rows)
    float*   s_esq   = (float*)(smem + OFF_ESQ);           // 512 (approx)
    float*   s_rowsq = (float*)(smem + OFF_ROWSQ);         // 64 (exact chains)

    const int tid = threadIdx.x;
    const int wid = tid >> 5, tx = tid & 31;
    const long long row0 = (long long)blockIdx.x * TM;

    // --- stage latents as fp16 (d,d+1) pairs ---
    {
        const float4* lat4 = (const float4*)(latents + row0 * D_DIM);
#pragma unroll
        for (int it = 0; it < 8; ++it) {
            int idx = it * NTHREADS + tid;      // 2048 float4
            int row = idx >> 5, c4 = idx & 31;
            float4 x = lat4[idx];
            s_lath[row * 64 + c4 * 2]     = __floats2half2_rn(x.x, x.y);
            s_lath[row * 64 + c4 * 2 + 1] = __floats2half2_rn(x.z, x.w);
        }
    }
    // --- rowsq: exact sequential reference chain (rescue/cm only) ---
    if (tid < TM) {
        const float* lr = latents + (row0 + tid) * D_DIM;
        float s = 0.f;
        for (int d = 0; d < D_DIM; ++d)
            s = __fadd_rn(s, __fmul_rn(lr[d], lr[d]));
        s_rowsq[tid] = s;
    }

    const int r0 = wid * 8;     // 8 rows per warp
    float usum[8], umax[8];
#pragma unroll
    for (int i = 0; i < 8; ++i) { usum[i] = 0.f; umax[i] = 0.f; }
    const __half2 hz = __float2half2_rn(0.f);

    const unsigned char* aBase = smem + OFF_LATH + (size_t)r0 * ALSTR;
    const unsigned char* bBase = smem + OFF_EMB + (size_t)tx * ESTR;

    // ---- 8 stages of 64 k-rows: fill fp16 (x256), R8xC2 HFMA2 GEMM, u -> fp16 smem ----
#pragma unroll 1
    for (int s = 0; s < 8; ++s) {
        __syncthreads();   // prior stage's reads done before overwrite
        {
            // fill: 4 threads per k-row, 32 d each (validated r12)
            int t = tid >> 2, p = tid & 3;
            const float4* src = (const float4*)emb + (size_t)(s * 64 + t) * 32 + p * 8;
            unsigned char* dst = smem + OFF_EMB + t * ESTR + p * 64;
            float ep = 0.f;
#pragma unroll
            for (int jj = 0; jj < 8; ++jj) {
                float4 v = src[jj];
                ep += v.x * v.x + v.y * v.y + v.z * v.z + v.w * v.w;
                union { __half2 h[2]; uint2 u; } pk;
                pk.h[0] = __floats2half2_rn(v.x * 256.f, v.y * 256.f);
                pk.h[1] = __floats2half2_rn(v.z * 256.f, v.w * 256.f);
                *(uint2*)(dst + jj * 8) = pk.u;
            }
            ep += __shfl_xor_sync(0xffffffffu, ep, 1);
            ep += __shfl_xor_sync(0xffffffffu, ep, 2);
            if (p == 0) s_esq[s * 64 + t] = ep;
        }
        __syncthreads();

        float accF[8][2];
        __half2 accH[8][2];
#pragma unroll
        for (int i = 0; i < 8; ++i)
#pragma unroll
            for (int j = 0; j < 2; ++j) { accF[i][j] = 0.f; accH[i][j] = hz; }

#pragma unroll 1
        for (int chunk = 0; chunk < 4; ++chunk) {
#pragma unroll
            for (int d4 = 0; d4 < 8; ++d4) {
                int off = (chunk * 8 + d4) * 8;          // 4 d values per iter
                union { __half2 h[2]; uint2 u; } av[8], bv[2];
#pragma unroll
                for (int i = 0; i < 8; ++i)
                    av[i].u = *(const uint2*)(aBase + i * ALSTR + off);   // broadcast
#pragma unroll
                for (int j = 0; j < 2; ++j)
                    bv[j].u = *(const uint2*)(bBase + j * (32 * ESTR) + off);
#pragma unroll
                for (int i = 0; i < 8; ++i)
#pragma unroll
                    for (int j = 0; j < 2; ++j) {
                        accH[i][j] = __hfma2(av[i].h[0], bv[j].h[0], accH[i][j]);
                        accH[i][j] = __hfma2(av[i].h[1], bv[j].h[1], accH[i][j]);
                    }
            }
            // promote to fp32 every 32 d (validated error budget)
#pragma unroll
            for (int i = 0; i < 8; ++i)
#pragma unroll
                for (int j = 0; j < 2; ++j) {
                    float2 f = __half22float2(accH[i][j]);
                    accF[i][j] += f.x + f.y;
                    accH[i][j] = hz;
                }
        }

        // u = exp(-10 * (esq - dotS/128)) -> fp16 smem; track sum/max per row
#pragma unroll
        for (int j = 0; j < 2; ++j) {
            int k = s * 64 + tx + 32 * j;
            float es = s_esq[k];
#pragma unroll
            for (int i = 0; i < 8; ++i) {
                float dsh = __fmaf_rn(accF[i][j], -0.0078125f, es);
                float u = __expf(-BETA_SM * dsh);
                s_uh[(r0 + i) * USTRH + k] = __float2half_rn(u);
                usum[i] += u;
                umax[i] = fmaxf(umax[i], u);
            }
        }
    }

    // ---- warp-reduce per-row sum/max ----
#pragma unroll
    for (int i = 0; i < 8; ++i)
#pragma unroll
        for (int o = 16; o; o >>= 1) {
            usum[i] += __shfl_xor_sync(0xffffffffu, usum[i], o);
            umax[i] = fmaxf(umax[i], __shfl_xor_sync(0xffffffffu, umax[i], o));
        }

    // ---- phase 2: probs, exact-rescue argmin, outputs ----
    float warp_sq = 0.f, warp_cm = 0.f;

#pragma unroll 1
    for (int i = 0; i < 8; ++i) {
        int r = r0 + i;
        long long rg = row0 + r;
        const __half* ur = s_uh + r * USTRH;
        float inv = 1.0f / usum[i];
        float thr = umax[i] * 0.994f;       // dist margin ~6e-4 (validated r12)

        float* os = out_soft + rg * K_DIM;
        const float rsq = s_rowsq[r];
        const float* lrow = latents + rg * D_DIM;
        float bestd = 3.4e38f;
        int bestk = 0x7fffffff;
#pragma unroll 1
        for (int t = 0; t < 16; ++t) {
            int k = tx + 32 * t;
            float uv = __half2float(ur[k]);
            os[k] = uv * inv;
            if (uv >= thr) {
                // exact sequential-chain recompute on the reference grid
                const float* er = emb + (size_t)k * D_DIM;
                float a = 0.f, qq = 0.f;
                for (int d = 0; d < D_DIM; ++d) {
                    float ev = er[d];
                    a = __fmaf_rn(lrow[d], ev, a);
                    qq = __fadd_rn(qq, __fmul_rn(ev, ev));
                }
                float de = __fmaf_rn(-2.f, a, __fadd_rn(rsq, qq));
                if (de < bestd || (de == bestd && k < bestk)) { bestd = de; bestk = k; }
            }
        }
#pragma unroll
        for (int o = 16; o; o >>= 1) {
            float od = __shfl_xor_sync(0xffffffffu, bestd, o);
            int   ok = __shfl_xor_sync(0xffffffffu, bestk, o);
            if (od < bestd || (od == bestd && ok < bestk)) { bestd = od; bestk = ok; }
        }

        if (tx == 0) {
            atomicAdd(&g_counts[bestk], 1u);
            out_ind[rg] = (float)bestk;
            warp_cm += bestd;
        }

        float4 qv = ((const float4*)emb)[bestk * 32 + tx];
        float4 lv = ((const float4*)lrow)[tx];
        ((float4*)(out_q + rg * D_DIM))[tx] = qv;
        float dx = qv.x - lv.x, dy = qv.y - lv.y, dz = qv.z - lv.z, dw = qv.w - lv.w;
        float sq = dx * dx + dy * dy + dz * dz + dw * dw;
#pragma unroll
        for (int o = 16; o; o >>= 1) sq += __shfl_xor_sync(0xffffffffu, sq, o);
        if (tx == 0) warp_sq += sq;
    }

    if (tx == 0) {
        atomicAdd(&g_sq_sum, (double)warp_sq);
        atomicAdd(&g_mind_sum, (double)warp_cm);
    }

    // ---- last-block finalize: scalars + reset globals ----
    __shared__ int s_last;
    __threadfence();
    __syncthreads();
    if (tid == 0) {
        unsigned int t = atomicAdd(&g_done, 1u);
        s_last = (t == gridDim.x - 1u) ? 1 : 0;
    }
    __syncthreads();
    if (s_last) {
        __threadfence();
        float* red = (float*)smem;   // reuse u space
        double Bd = (double)gridDim.x * TM;
        float Bf = (float)Bd;
        float p0 = (float)g_counts[tid] / Bf;
        float p1 = (float)g_counts[tid + 256] / Bf;
        red[tid] = -p0 * logf(p0 + 1e-10f) - p1 * logf(p1 + 1e-10f);
        g_counts[tid] = 0u;
        g_counts[tid + 256] = 0u;
        __syncthreads();
        for (int s = 128; s > 0; s >>= 1) {
            if (tid < s) red[tid] += red[tid + s];
            __syncthreads();
        }
        if (tid == 0) {
            out_vq[0]  = (float)((g_sq_sum / (Bd * (double)D_DIM)) * 1.25);
            out_ent[0] = red[0];
            out_cm[0]  = (float)(g_mind_sum / Bd);
            g_sq_sum = 0.0;
            g_mind_sum = 0.0;
            g_done = 0u;
        }
    }
}

extern "C" void kernel_launch(void* const* d_in, const int* in_sizes, int n_in,
                              void* d_out, int out_size)
{
    const float* latents = (const float*)d_in[0];
    const float* emb     = (const float*)d_in[1];
    long long B = (long long)in_sizes[0] / D_DIM;

    float* out      = (float*)d_out;
    float* out_q    = out;
    float* out_vq   = out + B * D_DIM;
    float* out_ent  = out_vq + 1;
    float* out_ind  = out_ent + 1;
    float* out_soft = out_ind + B;
    float* out_cm   = out_soft + B * K_DIM;

    cudaFuncSetAttribute(vq_kernel, cudaFuncAttributeMaxDynamicSharedMemorySize, SMEM_BYTES);

    vq_kernel<<<(unsigned)(B / TM), NTHREADS, SMEM_BYTES>>>(
        latents, emb, out_q, out_ind, out_soft, out_vq, out_ent, out_cm);
}